// round 11
// baseline (speedup 1.0000x reference)
#include <cuda_runtime.h>
#include <stdint.h>

// Problem constants
#define NSAMP 1000000u
#define KMIX  64
#define DDIM  16
#define LSTRIDE 260              // padded words per L matrix (256 + 4)
#define TPB 512
#define SPT 4                    // samples per thread
#define SPB (TPB * SPT)          // 2048 samples per block

// Opaque 1 — global load ptxas cannot constant-fold; mad.lo.u32 by this value
// stays IMAD (FMA pipe), moving adds off the saturated ALU pipe.
__device__ uint32_t g_one = 1u;

// ---------------------------------------------------------------------------
// Threefry-2x32, key (0,42), partitionable counter (0,i), combine o0^o1.
// Input c42 = i + 42  (first keyschedule add prefolded by caller).
// Round adds and keyschedule adds are IMADs (FMA pipe); rotate+xor stay ALU.
// ---------------------------------------------------------------------------
__device__ __forceinline__ uint32_t tf_bits(uint32_t c42, uint32_t one) {
    uint32_t x1 = c42;
    uint32_t x0 = x1;                       // round-1 specialized (x0 starts 0)
    x1 = __funnelshift_l(x1, x1, 13) ^ x0;

#define TFR(r) { asm("mad.lo.u32 %0, %1, %2, %0;" : "+r"(x0) : "r"(x1), "r"(one)); \
                 x1 = __funnelshift_l(x1, x1, (r)) ^ x0; }
#define KADD(v, c) asm("mad.lo.u32 %0, %1, %2, %0;" : "+r"(v) : "r"(one), "n"(c))
    TFR(15) TFR(26) TFR(6)
    KADD(x0, 42);          KADD(x1, 0x1BD11BF1);   // ks2+1
    TFR(17) TFR(29) TFR(16) TFR(24)
    KADD(x0, 0x1BD11BF0);  KADD(x1, 2);            // ks2 ; ks0+2
    TFR(13) TFR(15) TFR(26) TFR(6)
    /* x0 += ks0 (=0): skip */ KADD(x1, 45);       // ks1+3
    TFR(17) TFR(29) TFR(16) TFR(24)
    KADD(x0, 42);          KADD(x1, 0x1BD11BF4);   // ks1 ; ks2+4
    TFR(13) TFR(15) TFR(26) TFR(6)
    KADD(x0, 0x1BD11BF0);  KADD(x1, 5);            // ks2 ; ks0+5
#undef TFR
#undef KADD
    return x0 ^ x1;
}

// ---------------------------------------------------------------------------
// Fused kernel, 512 threads, 4 samples/thread (k-interleaved so one w2[k]
// LDS serves 4 elements). Ls+means staged in padded shared. Screen:
// argmin_k log2(u_k)*(-ln2/p_k); exact reference-formula rescan when the
// top-2 margin < 1e-3 + 1e-3*m1 (>=130x worst-case MUFU.LG2 error).
// ---------------------------------------------------------------------------
__global__ __launch_bounds__(TPB, 2) void fused_kernel(
    const float* __restrict__ pi,
    const float* __restrict__ x,
    const float* __restrict__ means,
    const float* __restrict__ Ls,
    float* __restrict__ y)
{
    extern __shared__ float sm[];
    float* sL   = sm;                        // 64 * 260 words
    float* sMu  = sm + KMIX * LSTRIDE;       // 1024 words
    float* sW2n = sMu + KMIX * DDIM;         // 64
    float* sLg  = sW2n + KMIX;               // 64
    __shared__ float sSum;

    int tid = threadIdx.x;

    // Stage Ls into padded shared (coalesced float4 loads).
    #pragma unroll
    for (int i = tid; i < KMIX * 64; i += TPB) {
        int k = i >> 6, r = i & 63;
        float4 v = __ldg((const float4*)Ls + i);
        *(float4*)(sL + k * LSTRIDE + r * 4) = v;
    }
    if (tid < 256) {
        float4 v = __ldg((const float4*)means + tid);
        *(float4*)(sMu + tid * 4) = v;
    }
    if (tid == 0) {                          // serial sum order: bit-identical
        float s = 0.0f;                      // to all verified runs
        for (int k = 0; k < KMIX; k++) s += pi[k];
        sSum = s;
    }
    __syncthreads();
    if (tid < KMIX) {
        float ssum = sSum;
        sLg[tid]  = logf(pi[tid] / ssum);
        sW2n[tid] = -0.6931471805599453f * (ssum / pi[tid]);  // -ln2/p_k
    }
    __syncthreads();

    uint32_t one = g_one;                    // opaque 1 (global load)

    const float INF = __int_as_float(0x7F800000);
    uint32_t b42[SPT];
    float m1[SPT], m2[SPT];
    int zi[SPT];

    #pragma unroll
    for (int j = 0; j < SPT; j++) {
        unsigned n  = blockIdx.x * SPB + j * TPB + tid;
        unsigned nc = n < NSAMP ? n : (NSAMP - 1u);
        b42[j] = nc * 64u + 42u;
        m1[j] = INF; m2[j] = INF; zi[j] = 0;
    }

    // ---- categorical sampling: k outer, 4 samples inner ----
    #pragma unroll 2
    for (int k = 0; k < KMIX; k++) {
        float w2 = sW2n[k];                  // one LDS for 4 elements
        #pragma unroll
        for (int j = 0; j < SPT; j++) {
            uint32_t bits = tf_bits(b42[j] + (uint32_t)k, one);
            uint32_t fb;
            // fb = (bits >> 9) + 0x3F800000 in one IMAD.HI (FMA pipe)
            asm("mad.hi.u32 %0, %1, %2, %3;"
                : "=r"(fb) : "r"(bits), "r"(0x00800000u), "r"(0x3F800000u));
            float u = __uint_as_float(fb) - 1.0f;        // [0,1)
            float m = __log2f(u) * w2;                   // >=0 (u=0 -> +inf)
            if (m < m1[j]) { m2[j] = m1[j]; m1[j] = m; zi[j] = k; }
            else           { m2[j] = fminf(m2[j], m); }
        }
    }

    // ---- recheck + matvec + store, per sample ----
    #pragma unroll 1
    for (int j = 0; j < SPT; j++) {
        int z = zi[j];
        if (m2[j] - m1[j] < 1e-3f + 1e-3f * m1[j]) {
            // Exact reference-formula rescan (verified bit-exact path).
            float best = -INF;
            int zb = 0;
            for (int k = 0; k < KMIX; k++) {
                uint32_t bits = tf_bits(b42[j] + (uint32_t)k, one);
                float f  = __uint_as_float(0x3F800000u | (bits >> 9)) - 1.0f;
                float uu = fmaxf(f, 1.17549435e-38f);
                float v  = -logf(-logf(uu)) + sLg[k];
                if (v > best) { best = v; zb = k; }
            }
            z = zb;
        }

        unsigned n  = blockIdx.x * SPB + j * TPB + tid;
        unsigned nc = n < NSAMP ? n : (NSAMP - 1u);

        const float4* xg = (const float4*)x + nc * 4;
        float4 xa = __ldg(xg + 0);
        float4 xb = __ldg(xg + 1);
        float4 xc = __ldg(xg + 2);
        float4 xd = __ldg(xg + 3);
        float xr[16] = { xa.x, xa.y, xa.z, xa.w,
                         xb.x, xb.y, xb.z, xb.w,
                         xc.x, xc.y, xc.z, xc.w,
                         xd.x, xd.y, xd.z, xd.w };

        const float* Lb = sL + z * LSTRIDE;
        const float* Mb = sMu + z * DDIM;
        float4 acc0 = *(const float4*)(Mb + 0);
        float4 acc1 = *(const float4*)(Mb + 4);
        float4 acc2 = *(const float4*)(Mb + 8);
        float4 acc3 = *(const float4*)(Mb + 12);

        #pragma unroll
        for (int d = 0; d < DDIM; d++) {
            float xs = xr[d];
            float4 l0 = *(const float4*)(Lb + d * 16 + 0);
            float4 l1 = *(const float4*)(Lb + d * 16 + 4);
            float4 l2 = *(const float4*)(Lb + d * 16 + 8);
            float4 l3 = *(const float4*)(Lb + d * 16 + 12);
            acc0.x = fmaf(xs, l0.x, acc0.x); acc0.y = fmaf(xs, l0.y, acc0.y);
            acc0.z = fmaf(xs, l0.z, acc0.z); acc0.w = fmaf(xs, l0.w, acc0.w);
            acc1.x = fmaf(xs, l1.x, acc1.x); acc1.y = fmaf(xs, l1.y, acc1.y);
            acc1.z = fmaf(xs, l1.z, acc1.z); acc1.w = fmaf(xs, l1.w, acc1.w);
            acc2.x = fmaf(xs, l2.x, acc2.x); acc2.y = fmaf(xs, l2.y, acc2.y);
            acc2.z = fmaf(xs, l2.z, acc2.z); acc2.w = fmaf(xs, l2.w, acc2.w);
            acc3.x = fmaf(xs, l3.x, acc3.x); acc3.y = fmaf(xs, l3.y, acc3.y);
            acc3.z = fmaf(xs, l3.z, acc3.z); acc3.w = fmaf(xs, l3.w, acc3.w);
        }

        if (n < NSAMP) {
            float4* y4 = (float4*)y + n * 4;
            y4[0] = acc0; y4[1] = acc1; y4[2] = acc2; y4[3] = acc3;
        }
    }
}

// ---------------------------------------------------------------------------
extern "C" void kernel_launch(void* const* d_in, const int* in_sizes, int n_in,
                              void* d_out, int out_size) {
    const float* x     = (const float*)d_in[0];   // (N, D)
    const float* pi    = (const float*)d_in[1];   // (K,)
    const float* means = (const float*)d_in[2];   // (K, D)
    const float* Ls    = (const float*)d_in[3];   // (K, D, D)
    float* y           = (float*)d_out;           // (N, D)

    const int smem_bytes = (KMIX * LSTRIDE + KMIX * DDIM + KMIX + KMIX) * 4;
    cudaFuncSetAttribute(fused_kernel,
                         cudaFuncAttributeMaxDynamicSharedMemorySize, smem_bytes);
    const unsigned grid = (NSAMP + SPB - 1u) / SPB;   // 489
    fused_kernel<<<grid, TPB, smem_bytes>>>(pi, x, means, Ls, y);
}

// round 12
// speedup vs baseline: 1.1676x; 1.1676x over previous
#include <cuda_runtime.h>
#include <stdint.h>

// Problem constants
#define NSAMP 1000000
#define KMIX  64
#define DDIM  16

// Opaque 1 — global load ptxas cannot constant-fold; mad.lo.u32 by this value
// stays IMAD (off the saturated ALU pipe).
__device__ uint32_t g_one = 1u;

// ---------------------------------------------------------------------------
// Threefry-2x32, key (0,42), partitionable counter (0,i), combine o0^o1.
// Input c42 = i + 42 (first keyschedule add prefolded by caller).
// The 20 round adds are forced IMADs; keyschedule adds stay plain C adds
// (ptxas alternates IMAD/IADD3 there on its own).
// ---------------------------------------------------------------------------
__device__ __forceinline__ uint32_t tf_bits(uint32_t c42, uint32_t one) {
    const uint32_t ks1 = 42u;
    const uint32_t ks2 = 0x1BD11BDAu ^ 42u;

    uint32_t x1 = c42;
    uint32_t x0 = x1;                       // round-1 specialized (x0 starts 0)
    x1 = __funnelshift_l(x1, x1, 13) ^ x0;

#define TFR(r) { asm("mad.lo.u32 %0, %1, %2, %0;" : "+r"(x0) : "r"(x1), "r"(one)); \
                 x1 = __funnelshift_l(x1, x1, (r)) ^ x0; }
    TFR(15) TFR(26) TFR(6)
    x0 += ks1;  x1 += ks2 + 1u;
    TFR(17) TFR(29) TFR(16) TFR(24)
    x0 += ks2;  x1 += 2u;                   // ks0 = 0
    TFR(13) TFR(15) TFR(26) TFR(6)
    /* x0 += ks0 (=0): skip */
    x1 += ks1 + 3u;
    TFR(17) TFR(29) TFR(16) TFR(24)
    x0 += ks1;  x1 += ks2 + 4u;
    TFR(13) TFR(15) TFR(26) TFR(6)
    x0 += ks2;  x1 += 5u;                   // ks0 = 0
#undef TFR
    return x0 ^ x1;
}

// ---------------------------------------------------------------------------
// Fused kernel (R6 structure): block-local logits -> per-thread sample ->
// per-thread __ldg matvec. Tiny smem footprint keeps occupancy high; the
// ALU pipe (threefry rotate/xor) is the bottleneck, L1 gathers overlap it.
// Screen: argmin_k log2(u_k)*(-ln2/p_k); exact reference-formula rescan when
// the top-2 margin < 1e-3 + 1e-3*m1 (>=130x worst-case MUFU.LG2 error).
// ---------------------------------------------------------------------------
__global__ __launch_bounds__(256) void fused_kernel(
    const float* __restrict__ pi,
    const float* __restrict__ x,
    const float* __restrict__ means,
    const float* __restrict__ Ls,
    float* __restrict__ y)
{
    __shared__ float s_w2n[KMIX];
    __shared__ float s_logit[KMIX];
    __shared__ float s_sum;

    // Block-local logits (serial sum order identical to verified runs).
    if (threadIdx.x == 0) {
        float s = 0.0f;
        for (int k = 0; k < KMIX; k++) s += pi[k];
        s_sum = s;
    }
    __syncthreads();
    if (threadIdx.x < KMIX) {
        float ssum = s_sum;
        s_logit[threadIdx.x] = logf(pi[threadIdx.x] / ssum);
        s_w2n[threadIdx.x]   = -0.6931471805599453f * (ssum / pi[threadIdx.x]);
    }
    __syncthreads();

    unsigned n = blockIdx.x * 256u + threadIdx.x;
    if (n >= NSAMP) return;

    uint32_t one = g_one;                    // opaque 1 (global load)
    uint32_t b42 = n * 64u + 42u;

    // ---- categorical sample (screen) ----
    const float INF = __int_as_float(0x7F800000);
    float m1 = INF, m2 = INF;
    int i1 = 0;

    #pragma unroll 8
    for (int k = 0; k < KMIX; k++) {
        uint32_t bits = tf_bits(b42 + (uint32_t)k, one);
        uint32_t fb;
        // fb = (bits >> 9) + 0x3F800000 in one IMAD.HI (off-ALU)
        asm("mad.hi.u32 %0, %1, %2, %3;"
            : "=r"(fb) : "r"(bits), "r"(0x00800000u), "r"(0x3F800000u));
        float u = __uint_as_float(fb) - 1.0f;           // [0,1)
        float m = __log2f(u) * s_w2n[k];                // >=0 (u=0 -> +inf, never min)
        if (m < m1) { m2 = m1; m1 = m; i1 = k; }
        else        { m2 = fminf(m2, m); }
    }

    int z = i1;
    if (m2 - m1 < 1e-3f + 1e-3f * m1) {
        // Exact reference-formula rescan (verified bit-exact path).
        float best = -INF;
        int zi = 0;
        for (int k = 0; k < KMIX; k++) {
            uint32_t bits = tf_bits(b42 + (uint32_t)k, one);
            float f  = __uint_as_float(0x3F800000u | (bits >> 9)) - 1.0f;
            float uu = fmaxf(f, 1.17549435e-38f);
            float v  = -logf(-logf(uu)) + s_logit[k];
            if (v > best) { best = v; zi = k; }
        }
        z = zi;
    }

    // ---- matvec: y[n] = x[n]^T @ L[z] + mu[z]  (R6 __ldg version) ----
    const float4* xg = (const float4*)x + n * 4;
    float4 xa = __ldg(xg + 0);
    float4 xb = __ldg(xg + 1);
    float4 xc = __ldg(xg + 2);
    float4 xd = __ldg(xg + 3);
    float xr[16] = { xa.x, xa.y, xa.z, xa.w,
                     xb.x, xb.y, xb.z, xb.w,
                     xc.x, xc.y, xc.z, xc.w,
                     xd.x, xd.y, xd.z, xd.w };

    const float4* L4 = (const float4*)Ls + z * 64;      // row d -> L4[d*4 + q]
    const float4* m4 = (const float4*)means + z * 4;

    float4 acc[4];
    #pragma unroll
    for (int q = 0; q < 4; q++) acc[q] = __ldg(m4 + q);

    #pragma unroll
    for (int d = 0; d < DDIM; d++) {
        float xs = xr[d];
        #pragma unroll
        for (int q = 0; q < 4; q++) {
            float4 lv = __ldg(L4 + d * 4 + q);
            acc[q].x = fmaf(xs, lv.x, acc[q].x);
            acc[q].y = fmaf(xs, lv.y, acc[q].y);
            acc[q].z = fmaf(xs, lv.z, acc[q].z);
            acc[q].w = fmaf(xs, lv.w, acc[q].w);
        }
    }

    float4* y4 = (float4*)y + n * 4;
    #pragma unroll
    for (int q = 0; q < 4; q++) y4[q] = acc[q];
}

// ---------------------------------------------------------------------------
extern "C" void kernel_launch(void* const* d_in, const int* in_sizes, int n_in,
                              void* d_out, int out_size) {
    const float* x     = (const float*)d_in[0];   // (N, D)
    const float* pi    = (const float*)d_in[1];   // (K,)
    const float* means = (const float*)d_in[2];   // (K, D)
    const float* Ls    = (const float*)d_in[3];   // (K, D, D)
    float* y           = (float*)d_out;           // (N, D)

    fused_kernel<<<(NSAMP + 255) / 256, 256>>>(pi, x, means, Ls, y);
}

// round 13
// speedup vs baseline: 1.3108x; 1.1227x over previous
#include <cuda_runtime.h>
#include <stdint.h>

// Problem constants
#define NSAMP 1000000
#define KMIX  64
#define DDIM  16

// Opaque 1 — global load ptxas cannot constant-fold; mad.lo.u32 by this value
// stays IMAD (off the saturated ALU pipe).
__device__ uint32_t g_one = 1u;

// ---------------------------------------------------------------------------
// Threefry-2x32, key (0,42), partitionable counter (0,i), combine o0^o1.
// Input c42 = i + 42 (first keyschedule add prefolded by caller).
// The 20 round adds are forced IMADs; keyschedule adds stay plain C adds.
// ---------------------------------------------------------------------------
__device__ __forceinline__ uint32_t tf_bits(uint32_t c42, uint32_t one) {
    const uint32_t ks1 = 42u;
    const uint32_t ks2 = 0x1BD11BDAu ^ 42u;

    uint32_t x1 = c42;
    uint32_t x0 = x1;                       // round-1 specialized (x0 starts 0)
    x1 = __funnelshift_l(x1, x1, 13) ^ x0;

#define TFR(r) { asm("mad.lo.u32 %0, %1, %2, %0;" : "+r"(x0) : "r"(x1), "r"(one)); \
                 x1 = __funnelshift_l(x1, x1, (r)) ^ x0; }
    TFR(15) TFR(26) TFR(6)
    x0 += ks1;  x1 += ks2 + 1u;
    TFR(17) TFR(29) TFR(16) TFR(24)
    x0 += ks2;  x1 += 2u;                   // ks0 = 0
    TFR(13) TFR(15) TFR(26) TFR(6)
    /* x0 += ks0 (=0): skip */
    x1 += ks1 + 3u;
    TFR(17) TFR(29) TFR(16) TFR(24)
    x0 += ks1;  x1 += ks2 + 4u;
    TFR(13) TFR(15) TFR(26) TFR(6)
    x0 += ks2;  x1 += 5u;                   // ks0 = 0
#undef TFR
    return x0 ^ x1;
}

// ---------------------------------------------------------------------------
// Fused kernel: per-thread categorical sample (verified path), then a
// warp-cooperative matvec: 4 passes, 4 lanes per sample (z via shfl), so
// L-row gathers are 64B-contiguous per 4-lane group — ~3-4x fewer L1tex
// wavefronts than the per-thread gather version (the measured binder).
// ---------------------------------------------------------------------------
__global__ __launch_bounds__(256) void fused_kernel(
    const float* __restrict__ pi,
    const float* __restrict__ x,
    const float* __restrict__ means,
    const float* __restrict__ Ls,
    float* __restrict__ y)
{
    __shared__ float s_w2n[KMIX];
    __shared__ float s_logit[KMIX];
    __shared__ float s_sum;

    // Block-local logits (serial sum order identical to verified runs).
    if (threadIdx.x == 0) {
        float s = 0.0f;
        for (int k = 0; k < KMIX; k++) s += pi[k];
        s_sum = s;
    }
    __syncthreads();
    if (threadIdx.x < KMIX) {
        float ssum = s_sum;
        s_logit[threadIdx.x] = logf(pi[threadIdx.x] / ssum);
        s_w2n[threadIdx.x]   = -0.6931471805599453f * (ssum / pi[threadIdx.x]);
    }
    __syncthreads();

    unsigned blockBase = blockIdx.x * 256u;
    unsigned warpBase  = blockBase + (threadIdx.x & ~31u);
    if (warpBase >= NSAMP) return;           // whole-warp guard (NSAMP % 32 == 0)

    unsigned n   = blockBase + threadIdx.x;  // this thread's sample (valid)
    int     lane = threadIdx.x & 31;

    uint32_t one = g_one;                    // opaque 1 (global load)
    uint32_t b42 = n * 64u + 42u;

    // ---- categorical sample (screen) ----
    const float INF = __int_as_float(0x7F800000);
    float m1 = INF, m2 = INF;
    int i1 = 0;

    #pragma unroll 8
    for (int k = 0; k < KMIX; k++) {
        uint32_t bits = tf_bits(b42 + (uint32_t)k, one);
        uint32_t fb;
        // fb = (bits >> 9) + 0x3F800000 in one IMAD.HI (off-ALU)
        asm("mad.hi.u32 %0, %1, %2, %3;"
            : "=r"(fb) : "r"(bits), "r"(0x00800000u), "r"(0x3F800000u));
        float u = __uint_as_float(fb) - 1.0f;           // [0,1)
        float m = __log2f(u) * s_w2n[k];                // >=0 (u=0 -> +inf, never min)
        if (m < m1) { m2 = m1; m1 = m; i1 = k; }
        else        { m2 = fminf(m2, m); }
    }

    int z = i1;
    if (m2 - m1 < 1e-3f + 1e-3f * m1) {
        // Exact reference-formula rescan (verified bit-exact path).
        float best = -INF;
        int zi = 0;
        for (int k = 0; k < KMIX; k++) {
            uint32_t bits = tf_bits(b42 + (uint32_t)k, one);
            float f  = __uint_as_float(0x3F800000u | (bits >> 9)) - 1.0f;
            float uu = fmaxf(f, 1.17549435e-38f);
            float v  = -logf(-logf(uu)) + s_logit[k];
            if (v > best) { best = v; zi = k; }
        }
        z = zi;
    }

    // ---- warp-cooperative matvec: 4 passes, 4 lanes per sample ----
    int q = lane & 3;                        // output quarter (e = 4q..4q+3)

    #pragma unroll 1
    for (int pass = 0; pass < 4; pass++) {
        int src = pass * 8 + (lane >> 2);    // lane that sampled this pass's z
        int zz  = __shfl_sync(0xFFFFFFFFu, z, src);
        unsigned ns = warpBase + (unsigned)src;

        // x[ns]: 4 lanes per group load same addresses (L1 broadcast)
        const float4* xg = (const float4*)x + ns * 4;
        float4 xa = __ldg(xg + 0);
        float4 xb = __ldg(xg + 1);
        float4 xc = __ldg(xg + 2);
        float4 xd = __ldg(xg + 3);
        float xr[16] = { xa.x, xa.y, xa.z, xa.w,
                         xb.x, xb.y, xb.z, xb.w,
                         xc.x, xc.y, xc.z, xc.w,
                         xd.x, xd.y, xd.z, xd.w };

        const float4* L4 = (const float4*)Ls + zz * 64 + q;   // row d -> L4[d*4]
        float4 acc = __ldg((const float4*)means + zz * 4 + q);

        #pragma unroll
        for (int d = 0; d < DDIM; d++) {
            float4 lv = __ldg(L4 + d * 4);
            float xs = xr[d];
            acc.x = fmaf(xs, lv.x, acc.x);
            acc.y = fmaf(xs, lv.y, acc.y);
            acc.z = fmaf(xs, lv.z, acc.z);
            acc.w = fmaf(xs, lv.w, acc.w);
        }

        ((float4*)y)[ns * 4 + q] = acc;      // 512B contiguous per warp
    }
}

// ---------------------------------------------------------------------------
extern "C" void kernel_launch(void* const* d_in, const int* in_sizes, int n_in,
                              void* d_out, int out_size) {
    const float* x     = (const float*)d_in[0];   // (N, D)
    const float* pi    = (const float*)d_in[1];   // (K,)
    const float* means = (const float*)d_in[2];   // (K, D)
    const float* Ls    = (const float*)d_in[3];   // (K, D, D)
    float* y           = (float*)d_out;           // (N, D)

    fused_kernel<<<(NSAMP + 255) / 256, 256>>>(pi, x, means, Ls, y);
}

// round 14
// speedup vs baseline: 1.4327x; 1.0930x over previous
#include <cuda_runtime.h>
#include <stdint.h>

// Problem constants
#define NSAMP 1000000
#define KMIX  64
#define DDIM  16

// Opaque 1 — global load ptxas cannot constant-fold; mad.lo.u32 by this value
// stays IMAD (off the saturated ALU pipe).
__device__ uint32_t g_one = 1u;

// ---------------------------------------------------------------------------
// Threefry-2x32, key (0,42), partitionable counter (0,i), combine o0^o1.
// Input c42 = i + 42 (first keyschedule add prefolded by caller).
// Round adds AND keyschedule adds are forced IMADs (off-ALU); rotate+xor
// (SHF+LOP3) are the irreducible ALU floor.
// ---------------------------------------------------------------------------
__device__ __forceinline__ uint32_t tf_bits(uint32_t c42, uint32_t one) {
    uint32_t x1 = c42;
    uint32_t x0 = x1;                       // round-1 specialized (x0 starts 0)
    x1 = __funnelshift_l(x1, x1, 13) ^ x0;

#define TFR(r) { asm("mad.lo.u32 %0, %1, %2, %0;" : "+r"(x0) : "r"(x1), "r"(one)); \
                 x1 = __funnelshift_l(x1, x1, (r)) ^ x0; }
#define KADD(v, c) asm("mad.lo.u32 %0, %1, %2, %0;" : "+r"(v) : "r"(one), "n"(c))
    TFR(15) TFR(26) TFR(6)
    KADD(x0, 42);          KADD(x1, 0x1BD11BF1);   // ks2+1
    TFR(17) TFR(29) TFR(16) TFR(24)
    KADD(x0, 0x1BD11BF0);  KADD(x1, 2);            // ks2 ; ks0+2
    TFR(13) TFR(15) TFR(26) TFR(6)
    /* x0 += ks0 (=0): skip */ KADD(x1, 45);       // ks1+3
    TFR(17) TFR(29) TFR(16) TFR(24)
    KADD(x0, 42);          KADD(x1, 0x1BD11BF4);   // ks1 ; ks2+4
    TFR(13) TFR(15) TFR(26) TFR(6)
    KADD(x0, 0x1BD11BF0);  KADD(x1, 5);            // ks2 ; ks0+5
#undef TFR
#undef KADD
    return x0 ^ x1;
}

// ---------------------------------------------------------------------------
// Fused kernel: per-thread categorical sample, then warp-cooperative matvec
// (4 passes, 4 lanes/sample, z via shfl) — verified to kill the L1tex
// wavefront bottleneck. Screen: argmin_k log2(u_k)*(-ln2/p_k); exact
// reference-formula rescan when top-2 margin < 4e-4 + 4e-4*m1 (3.3x the
// worst-case 1.2e-4 MUFU.LG2-induced error on the margin — any true flip
// forces the margin below 1.2e-4, so it is always rescanned).
// ---------------------------------------------------------------------------
__global__ __launch_bounds__(256) void fused_kernel(
    const float* __restrict__ pi,
    const float* __restrict__ x,
    const float* __restrict__ means,
    const float* __restrict__ Ls,
    float* __restrict__ y)
{
    __shared__ float s_w2n[KMIX];
    __shared__ float s_logit[KMIX];
    __shared__ float s_sum;

    // Block-local logits (serial sum order identical to verified runs).
    if (threadIdx.x == 0) {
        float s = 0.0f;
        for (int k = 0; k < KMIX; k++) s += pi[k];
        s_sum = s;
    }
    __syncthreads();
    if (threadIdx.x < KMIX) {
        float ssum = s_sum;
        s_logit[threadIdx.x] = logf(pi[threadIdx.x] / ssum);
        s_w2n[threadIdx.x]   = -0.6931471805599453f * (ssum / pi[threadIdx.x]);
    }
    __syncthreads();

    unsigned blockBase = blockIdx.x * 256u;
    unsigned warpBase  = blockBase + (threadIdx.x & ~31u);
    if (warpBase >= NSAMP) return;           // whole-warp guard (NSAMP % 32 == 0)

    unsigned n   = blockBase + threadIdx.x;  // this thread's sample (valid)
    int     lane = threadIdx.x & 31;

    uint32_t one = g_one;                    // opaque 1 (global load)
    uint32_t b42 = n * 64u + 42u;

    // ---- categorical sample (screen) ----
    const float INF = __int_as_float(0x7F800000);
    float m1 = INF, m2 = INF;
    int i1 = 0;

    #pragma unroll 8
    for (int k = 0; k < KMIX; k++) {
        uint32_t bits = tf_bits(b42 + (uint32_t)k, one);
        uint32_t fb;
        // fb = (bits >> 9) + 0x3F800000 in one IMAD.HI (off-ALU)
        asm("mad.hi.u32 %0, %1, %2, %3;"
            : "=r"(fb) : "r"(bits), "r"(0x00800000u), "r"(0x3F800000u));
        float u = __uint_as_float(fb) - 1.0f;           // [0,1)
        float m = __log2f(u) * s_w2n[k];                // >=0 (u=0 -> +inf, never min)
        if (m < m1) { m2 = m1; m1 = m; i1 = k; }
        else        { m2 = fminf(m2, m); }
    }

    int z = i1;
    if (m2 - m1 < 4e-4f + 4e-4f * m1) {
        // Exact reference-formula rescan (verified bit-exact path).
        float best = -INF;
        int zi = 0;
        for (int k = 0; k < KMIX; k++) {
            uint32_t bits = tf_bits(b42 + (uint32_t)k, one);
            float f  = __uint_as_float(0x3F800000u | (bits >> 9)) - 1.0f;
            float uu = fmaxf(f, 1.17549435e-38f);
            float v  = -logf(-logf(uu)) + s_logit[k];
            if (v > best) { best = v; zi = k; }
        }
        z = zi;
    }

    // ---- warp-cooperative matvec: 4 passes, 4 lanes per sample ----
    int q = lane & 3;                        // output quarter (e = 4q..4q+3)

    #pragma unroll 1
    for (int pass = 0; pass < 4; pass++) {
        int src = pass * 8 + (lane >> 2);    // lane that sampled this pass's z
        int zz  = __shfl_sync(0xFFFFFFFFu, z, src);
        unsigned ns = warpBase + (unsigned)src;

        // x[ns]: 4 lanes per group load same addresses (L1 broadcast)
        const float4* xg = (const float4*)x + ns * 4;
        float4 xa = __ldg(xg + 0);
        float4 xb = __ldg(xg + 1);
        float4 xc = __ldg(xg + 2);
        float4 xd = __ldg(xg + 3);
        float xr[16] = { xa.x, xa.y, xa.z, xa.w,
                         xb.x, xb.y, xb.z, xb.w,
                         xc.x, xc.y, xc.z, xc.w,
                         xd.x, xd.y, xd.z, xd.w };

        const float4* L4 = (const float4*)Ls + zz * 64 + q;   // row d -> L4[d*4]
        float4 acc = __ldg((const float4*)means + zz * 4 + q);

        #pragma unroll
        for (int d = 0; d < DDIM; d++) {
            float4 lv = __ldg(L4 + d * 4);
            float xs = xr[d];
            acc.x = fmaf(xs, lv.x, acc.x);
            acc.y = fmaf(xs, lv.y, acc.y);
            acc.z = fmaf(xs, lv.z, acc.z);
            acc.w = fmaf(xs, lv.w, acc.w);
        }

        ((float4*)y)[ns * 4 + q] = acc;      // 512B contiguous per warp
    }
}

// ---------------------------------------------------------------------------
extern "C" void kernel_launch(void* const* d_in, const int* in_sizes, int n_in,
                              void* d_out, int out_size) {
    const float* x     = (const float*)d_in[0];   // (N, D)
    const float* pi    = (const float*)d_in[1];   // (K,)
    const float* means = (const float*)d_in[2];   // (K, D)
    const float* Ls    = (const float*)d_in[3];   // (K, D, D)
    float* y           = (float*)d_out;           // (N, D)

    fused_kernel<<<(NSAMP + 255) / 256, 256>>>(pi, x, means, Ls, y);
}